// round 9
// baseline (speedup 1.0000x reference)
#include <cuda_runtime.h>

// Shapes: x (16,512,256) f32, target (16,512) i32, max_length 6144.
// Output = [output (16,6144,256) f32][duration_pred (16,512) f32=9.0]

#define NB   16
#define LSEQ 512
#define DDIM 256
#define ROW4 (DDIM / 4)          // 64 float4 per row
#define MLMAX 6144
#define SETUP_SPLIT 8            // setup blocks per batch

// Per-output-row source index; -1 => zero row.
__device__ int g_idx[NB * MLMAX];

// Grid (SETUP_SPLIT, NB) x 512. Every block redundantly scans its batch's
// durations (cheap), then scatters only its 1/SETUP_SPLIT window of g_idx.
__global__ void __launch_bounds__(LSEQ)
setup_kernel(const int* __restrict__ target,
             float* __restrict__ dur_out,
             int max_length)
{
    const int n    = blockIdx.y;
    const int q    = blockIdx.x;
    const int tid  = threadIdx.x;
    const int wid  = tid >> 5;
    const int lane = tid & 31;

    __shared__ int warp_sums[16];

    const int d = target[n * LSEQ + tid];
    int v = d;
    #pragma unroll
    for (int off = 1; off < 32; off <<= 1) {
        int u = __shfl_up_sync(0xffffffffu, v, off);
        if (lane >= off) v += u;
    }
    if (lane == 31) warp_sums[wid] = v;
    __syncthreads();
    if (wid == 0 && lane < 16) {
        int w = warp_sums[lane];
        #pragma unroll
        for (int off = 1; off < 16; off <<= 1) {
            int u = __shfl_up_sync(0x0000ffffu, w, off);
            if (lane >= off) w += u;
        }
        warp_sums[lane] = w;
    }
    __syncthreads();

    const int cur   = v + (wid ? warp_sums[wid - 1] : 0);
    const int prev  = cur - d;
    const int total = warp_sums[15];

    const int win   = max_length / SETUP_SPLIT;       // 768
    const int w0    = q * win;
    const int w1    = w0 + win;

    int* idx = g_idx + n * max_length;

    const int lo = prev > w0 ? prev : w0;
    const int hi = cur  < w1 ? cur  : w1;
    for (int t = lo; t < hi; ++t)
        idx[t] = tid;

    for (int t = w0 + tid; t < w1; t += LSEQ)
        if (t >= total) idx[t] = -1;

    if (q == 0)
        dur_out[n * LSEQ + tid] = 9.0f;
}

// Grid (max_length/32, NB) x 256. Each 64-thread group owns 8 consecutive
// output rows at fixed column d4. Indices are monotone within the group, so
// duplicate source rows are deduped in registers: only distinct rows load
// (warp-uniform predicates -> skipped loads are free). Tail (-1) folds into
// the same chain. No syncs, no smem, no division.
__global__ void __launch_bounds__(256)
gather_kernel(const float4* __restrict__ x4,
              float4*       __restrict__ out4,
              int max_length)
{
    const int n   = blockIdx.y;
    const int tid = threadIdx.x;
    const int d4  = tid & 63;
    const int r0  = blockIdx.x * 32 + (tid >> 6) * 8;   // first of 8 rows

    const int* ib = g_idx + n * max_length + r0;
    const int4 sa = *(const int4*)(ib);
    const int4 sb = *(const int4*)(ib + 4);
    const int s[8] = { sa.x, sa.y, sa.z, sa.w, sb.x, sb.y, sb.z, sb.w };

    const float4* __restrict__ xb = x4 + (long)n * LSEQ * ROW4 + d4;
    float4*       __restrict__ ob = out4 + ((long)n * max_length + r0) * ROW4 + d4;

    const float4 zero = make_float4(0.f, 0.f, 0.f, 0.f);

    float4 v[8];
    v[0] = (s[0] >= 0) ? xb[s[0] * ROW4] : zero;
    #pragma unroll
    for (int k = 1; k < 8; ++k) {
        if (s[k] == s[k - 1])
            v[k] = v[k - 1];                     // register reuse (common case)
        else
            v[k] = (s[k] >= 0) ? xb[s[k] * ROW4] : zero;
    }

    #pragma unroll
    for (int k = 0; k < 8; ++k)
        ob[k * ROW4] = v[k];
}

extern "C" void kernel_launch(void* const* d_in, const int* in_sizes, int n_in,
                              void* d_out, int out_size)
{
    const float* x      = (const float*)d_in[1];
    const int*   target = (const int*)  d_in[2];

    const int NL = in_sizes[2];                       // N*L = 8192
    const int max_length = (out_size - NL) / (NB * DDIM);

    float* out     = (float*)d_out;
    float* dur_out = out + (long)NB * max_length * DDIM;

    dim3 sgrid(SETUP_SPLIT, NB);                      // (8, 16)
    setup_kernel<<<sgrid, LSEQ>>>(target, dur_out, max_length);

    dim3 grid(max_length / 32, NB);                   // (192, 16)
    gather_kernel<<<grid, 256>>>((const float4*)x, (float4*)out, max_length);
}

// round 12
// speedup vs baseline: 1.0286x; 1.0286x over previous
#include <cuda_runtime.h>

// Shapes: x (16,512,256) f32, target (16,512) i32, max_length 6144.
// Output = [output (16,6144,256) f32][duration_pred (16,512) f32=9.0]
// Durations in [3,12]; per-batch total <= 512*12 = 6144 = max_length.

#define NB   16
#define LSEQ 512
#define DDIM 256
#define ROW4 (DDIM / 4)          // 64 float4 per row

__device__ int g_csum[NB * LSEQ];

// 16 blocks x 512: shfl scan -> g_csum, plus 9.0 buffer.
__global__ void __launch_bounds__(LSEQ)
setup_kernel(const int* __restrict__ target, float* __restrict__ dur_out)
{
    const int n    = blockIdx.x;
    const int tid  = threadIdx.x;
    const int wid  = tid >> 5;
    const int lane = tid & 31;

    __shared__ int warp_sums[16];

    int v = target[n * LSEQ + tid];
    #pragma unroll
    for (int off = 1; off < 32; off <<= 1) {
        int u = __shfl_up_sync(0xffffffffu, v, off);
        if (lane >= off) v += u;
    }
    if (lane == 31) warp_sums[wid] = v;
    __syncthreads();
    if (wid == 0 && lane < 16) {
        int w = warp_sums[lane];
        #pragma unroll
        for (int off = 1; off < 16; off <<= 1) {
            int u = __shfl_up_sync(0x0000ffffu, w, off);
            if (lane >= off) w += u;
        }
        warp_sums[lane] = w;
    }
    __syncthreads();

    g_csum[n * LSEQ + tid] = v + (wid ? warp_sums[wid - 1] : 0);
    dur_out[n * LSEQ + tid] = 9.0f;
}

// Source-driven scatter. Grid (LSEQ/8, NB) x 512: each 64-thread group owns
// one source row l; reads x[n,l,:] ONCE (one LDG.128 per thread), stores it
// to its dur output rows [prev,cur), then zero-fills tail rows total+l+512k.
// Loop bounds are warp-uniform (both warps of a group share l); every store
// is a coalesced 1KB row. Total read traffic: 8 MB.
__global__ void __launch_bounds__(LSEQ)
scatter_kernel(const float4* __restrict__ x4,
               float4*       __restrict__ out4,
               int max_length)
{
    const int n   = blockIdx.y;
    const int tid = threadIdx.x;
    const int d4  = tid & 63;
    const int l   = blockIdx.x * 8 + (tid >> 6);      // source row 0..511

    const int* cs = g_csum + n * LSEQ;
    const int cur   = cs[l];
    const int prev  = l ? cs[l - 1] : 0;
    const int total = cs[LSEQ - 1];

    // Read this source element once.
    const float4 v = x4[((long)n * LSEQ + l) * ROW4 + d4];

    float4* __restrict__ ob = out4 + (long)n * max_length * ROW4 + d4;

    // Replicate to [prev, cur): 3..12 coalesced row stores, warp-uniform.
    for (int t = prev; t < cur; ++t)
        ob[(long)t * ROW4] = v;

    // Tail zeros: rows total + l + 512k, warp-uniform count.
    const float4 zero = make_float4(0.f, 0.f, 0.f, 0.f);
    for (int t = total + l; t < max_length; t += LSEQ)
        ob[(long)t * ROW4] = zero;
}

extern "C" void kernel_launch(void* const* d_in, const int* in_sizes, int n_in,
                              void* d_out, int out_size)
{
    const float* x      = (const float*)d_in[1];
    const int*   target = (const int*)  d_in[2];

    const int NL = in_sizes[2];                       // N*L = 8192
    const int max_length = (out_size - NL) / (NB * DDIM);

    float* out     = (float*)d_out;
    float* dur_out = out + (long)NB * max_length * DDIM;

    setup_kernel<<<NB, LSEQ>>>(target, dur_out);

    dim3 grid(LSEQ / 8, NB);                          // (64, 16)
    scatter_kernel<<<grid, LSEQ>>>((const float4*)x, (float4*)out, max_length);
}

// round 14
// speedup vs baseline: 1.1206x; 1.0894x over previous
#include <cuda_runtime.h>

// Shapes: x (16,512,256) f32, target (16,512) i32, max_length 6144.
// Output = [output (16,6144,256) f32][duration_pred (16,512) f32=9.0]
// Durations in [3,12]; per-batch total <= 512*12 = 6144 = max_length.

#define NB   16
#define LSEQ 512
#define DDIM 256
#define ROW4 (DDIM / 4)          // 64 float4 per row

// Single fused kernel. Grid (LSEQ/8, NB) = (64,16), 512 threads.
// Prologue: coalesced load of target row (L2 broadcast), shfl scan -> smem.
// Body: each 64-thread group owns source row l; x[n,l,:] read once
// (hoisted above the scan to hide latency), stored to output rows
// [prev,cur); tail rows total+l+512k zero-filled. All loop bounds
// warp-uniform; all stores coalesced 1 KB rows.
__global__ void __launch_bounds__(LSEQ)
fused_scatter(const float4* __restrict__ x4,
              const int*    __restrict__ target,
              float4*       __restrict__ out4,
              float*        __restrict__ dur_out,
              int max_length)
{
    const int n    = blockIdx.y;
    const int tid  = threadIdx.x;
    const int wid  = tid >> 5;
    const int lane = tid & 31;
    const int d4   = tid & 63;
    const int l    = blockIdx.x * 8 + (tid >> 6);     // source row 0..511

    __shared__ int warp_sums[16];
    __shared__ int s_csum[LSEQ];

    // Issue the data load FIRST: independent of the scan, its ~600-cycle
    // latency hides under the scan + barriers below.
    const float4 v = x4[((long)n * LSEQ + l) * ROW4 + d4];

    // Inclusive scan of target[n, :] (one element per thread, coalesced).
    const int d = target[n * LSEQ + tid];
    int c = d;
    #pragma unroll
    for (int off = 1; off < 32; off <<= 1) {
        int u = __shfl_up_sync(0xffffffffu, c, off);
        if (lane >= off) c += u;
    }
    if (lane == 31) warp_sums[wid] = c;
    __syncthreads();
    if (wid == 0 && lane < 16) {
        int w = warp_sums[lane];
        #pragma unroll
        for (int off = 1; off < 16; off <<= 1) {
            int u = __shfl_up_sync(0x0000ffffu, w, off);
            if (lane >= off) w += u;
        }
        warp_sums[lane] = w;
    }
    __syncthreads();
    s_csum[tid] = c + (wid ? warp_sums[wid - 1] : 0);

    // duration_predictor_output = 9.0 (one block column per batch)
    if (blockIdx.x == 0)
        dur_out[n * LSEQ + tid] = 9.0f;

    __syncthreads();

    const int cur   = s_csum[l];
    const int prev  = l ? s_csum[l - 1] : 0;
    const int total = s_csum[LSEQ - 1];

    float4* __restrict__ ob = out4 + (long)n * max_length * ROW4 + d4;

    // Replicate to [prev, cur): 3..12 coalesced row stores, warp-uniform.
    for (int t = prev; t < cur; ++t)
        ob[(long)t * ROW4] = v;

    // Tail zeros: rows total + l + 512k, warp-uniform count.
    const float4 zero = make_float4(0.f, 0.f, 0.f, 0.f);
    for (int t = total + l; t < max_length; t += LSEQ)
        ob[(long)t * ROW4] = zero;
}

extern "C" void kernel_launch(void* const* d_in, const int* in_sizes, int n_in,
                              void* d_out, int out_size)
{
    const float* x      = (const float*)d_in[1];
    const int*   target = (const int*)  d_in[2];

    const int NL = in_sizes[2];                       // N*L = 8192
    const int max_length = (out_size - NL) / (NB * DDIM);

    float* out     = (float*)d_out;
    float* dur_out = out + (long)NB * max_length * DDIM;

    dim3 grid(LSEQ / 8, NB);                          // (64, 16)
    fused_scatter<<<grid, LSEQ>>>((const float4*)x, target,
                                  (float4*)out, dur_out, max_length);
}